// round 2
// baseline (speedup 1.0000x reference)
#include <cuda_runtime.h>

#define BATCH 128
#define NT 512

__device__ float g_partials[BATCH];
__device__ unsigned int g_count = 0;

__device__ __forceinline__ float warp_sum(float v) {
#pragma unroll
    for (int o = 16; o; o >>= 1) v += __shfl_down_sync(0xffffffffu, v, o);
    return v;
}

// One block per batch element. 512 threads. Fused final reduction (last block).
__global__ __launch_bounds__(NT, 1)
void loss_main(const float* __restrict__ input,
               const float* __restrict__ target,
               const float* __restrict__ normals,
               const float* __restrict__ param_mean,
               const float* __restrict__ param_std,
               const float* __restrict__ u,
               const float* __restrict__ w_shp,
               const float* __restrict__ w_exp,
               const int*   __restrict__ keyindex,
               const int*   __restrict__ ridx_w,
               const int*   __restrict__ ridx_v,
               float* __restrict__ out)
{
    const int n    = blockIdx.x;
    const int tid  = threadIdx.x;
    const int lane = tid & 31;
    const int wid  = tid >> 5;

    __shared__ float sp[62], spg[62];          // denormalized params
    __shared__ float bv[600], bvg[600];        // base verts on kmix_v (pred / gt)
    __shared__ float colsq_w[16][50];          // per-warp partial column sq-sums
    __shared__ float tn_w[16][3];              // per-warp partial tmpv sq-sums
    __shared__ float wcol[50];                 // column norms of w_cat (kmix_w rows)
    __shared__ float tnsq[3];                  // tmpv row sq-norms
    __shared__ float vt[200][3], vtg[200][3];  // rotated verts (kmix_v points)
    __shared__ float red[NT];                  // reduction scratch
    __shared__ int   s_last;

    // ---- 0. denormalize params ----
    if (tid < 62) {
        float st = param_std[tid], mn = param_mean[tid];
        sp[tid]  = input [n * 62 + tid] * st + mn;
        spg[tid] = target[n * 62 + tid] * st + mn;
    }
    __syncthreads();

    // ---- 1. kmix_w pass: pred base verts -> tmpv norms; fused column sq-norms.
    //         Rows 0..203 (keypoints) are shared with kmix_v: stash pred verts in bv.
    float csq[50];
#pragma unroll
    for (int k = 0; k < 50; k++) csq[k] = 0.f;
    float tn0 = 0.f, tn1 = 0.f, tn2 = 0.f;

    for (int l = tid; l < 600; l += NT) {
        int j = l / 3, c = l - 3 * j;
        int vid = (j < 68) ? keyindex[j] : ridx_w[j - 68];
        int r = 3 * vid + c;
        float s = u[r];
        const float4* w4 = (const float4*)(w_shp + (size_t)r * 40);
#pragma unroll
        for (int q = 0; q < 10; q++) {
            float4 v = w4[q];
            s += v.x * sp[12 + 4 * q] + v.y * sp[13 + 4 * q]
               + v.z * sp[14 + 4 * q] + v.w * sp[15 + 4 * q];
            csq[4 * q + 0] += v.x * v.x;
            csq[4 * q + 1] += v.y * v.y;
            csq[4 * q + 2] += v.z * v.z;
            csq[4 * q + 3] += v.w * v.w;
        }
        const float2* e2 = (const float2*)(w_exp + (size_t)r * 10);
#pragma unroll
        for (int q = 0; q < 5; q++) {
            float2 v = e2[q];
            s += v.x * sp[52 + 2 * q] + v.y * sp[53 + 2 * q];
            csq[40 + 2 * q] += v.x * v.x;
            csq[41 + 2 * q] += v.y * v.y;
        }
        if (l < 204) bv[l] = s;   // reuse for kmix_v (keypoint rows identical)
        float s2 = s * s;
        if (c == 0) tn0 += s2; else if (c == 1) tn1 += s2; else tn2 += s2;
    }
    tn0 = warp_sum(tn0); tn1 = warp_sum(tn1); tn2 = warp_sum(tn2);
    if (lane == 0) { tn_w[wid][0] = tn0; tn_w[wid][1] = tn1; tn_w[wid][2] = tn2; }
#pragma unroll
    for (int k = 0; k < 50; k++) {
        float v = warp_sum(csq[k]);
        if (lane == 0) colsq_w[wid][k] = v;
    }
    __syncthreads();
    if (tid < 50) {
        float s = 0.f;
#pragma unroll
        for (int w = 0; w < 16; w++) s += colsq_w[w][tid];
        wcol[tid] = sqrtf(s);
    }
    if (tid < 3) {
        float s = 0.f;
#pragma unroll
        for (int w = 0; w < 16; w++) s += tn_w[w][tid];
        tnsq[tid] = s;
    }

    // ---- 2. kmix_v base verts. l<204: pred already in bv, compute gt only. ----
    for (int l = tid; l < 600; l += NT) {
        int j = l / 3, c = l - 3 * j;
        int vid = (j < 68) ? keyindex[j] : ridx_v[j - 68];
        int r = 3 * vid + c;
        float uu = u[r];
        const float4* w4 = (const float4*)(w_shp + (size_t)r * 40);
        const float2* e2 = (const float2*)(w_exp + (size_t)r * 10);
        if (l < 204) {
            float sg = uu;
#pragma unroll
            for (int q = 0; q < 10; q++) {
                float4 v = w4[q];
                sg += v.x * spg[12 + 4 * q] + v.y * spg[13 + 4 * q]
                    + v.z * spg[14 + 4 * q] + v.w * spg[15 + 4 * q];
            }
#pragma unroll
            for (int q = 0; q < 5; q++) {
                float2 v = e2[q];
                sg += v.x * spg[52 + 2 * q] + v.y * spg[53 + 2 * q];
            }
            bvg[l] = sg;
        } else {
            float s = uu, sg = uu;
#pragma unroll
            for (int q = 0; q < 10; q++) {
                float4 v = w4[q];
                s  += v.x * sp [12 + 4 * q] + v.y * sp [13 + 4 * q]
                    + v.z * sp [14 + 4 * q] + v.w * sp [15 + 4 * q];
                sg += v.x * spg[12 + 4 * q] + v.y * spg[13 + 4 * q]
                    + v.z * spg[14 + 4 * q] + v.w * spg[15 + 4 * q];
            }
#pragma unroll
            for (int q = 0; q < 5; q++) {
                float2 v = e2[q];
                s  += v.x * sp [52 + 2 * q] + v.y * sp [53 + 2 * q];
                sg += v.x * spg[52 + 2 * q] + v.y * spg[53 + 2 * q];
            }
            bv[l] = s; bvg[l] = sg;
        }
    }
    __syncthreads();

    // ---- 3. weights + wpdc ----
    float wj = 0.f;
    if (tid < 62) {
        float pd = fabsf(sp[tid] - spg[tid]);
        if (tid < 11) {
            int cc = tid & 3;
            float sc = (cc < 3) ? sqrtf(tnsq[cc]) : 14.142135623730951f;  // sqrt(200)
            wj = pd * sc + 1e-6f;
        } else if (tid == 11) {
            wj = 1e-6f;
        } else {
            wj = 0.00057339936f * pd * wcol[tid - 12] + 1e-6f;
        }
    }
    red[tid] = wj;  // 0 for tid >= 62 (all real weights > 0)
    __syncthreads();
#pragma unroll
    for (int o = NT / 2; o; o >>= 1) {
        if (tid < o) red[tid] = fmaxf(red[tid], red[tid + o]);
        __syncthreads();
    }
    float wmax = red[0];
    __syncthreads();

    float wpdc = 0.f;
    if (tid < 62 && tid != 11) {
        float d = input[n * 62 + tid] - target[n * 62 + tid];
        wpdc = (wj / wmax) * d * d;
    }

    // ---- 4. rotate kmix_v verts: vt = R*b + off (y-flip cancels in all uses) ----
    if (tid < 200) {
        float b0 = bv [3 * tid], b1 = bv [3 * tid + 1], b2 = bv [3 * tid + 2];
        float c0 = bvg[3 * tid], c1 = bvg[3 * tid + 1], c2 = bvg[3 * tid + 2];
#pragma unroll
        for (int i = 0; i < 3; i++) {
            vt [tid][i] = sp [4 * i] * b0 + sp [4 * i + 1] * b1 + sp [4 * i + 2] * b2 + sp [4 * i + 3];
            vtg[tid][i] = spg[4 * i] * c0 + spg[4 * i + 1] * c1 + spg[4 * i + 2] * c2 + spg[4 * i + 3];
        }
    }
    __syncthreads();

    // ---- 5. chamfer (200x200) + nwl (68 landmarks, normals column-sums) ----
    float cham = 0.f, nwl = 0.f;
    if (tid < 200) {
        float x0 = vtg[tid][0], x1 = vtg[tid][1], x2 = vtg[tid][2];  // gt point
        float y0 = vt [tid][0], y1 = vt [tid][1], y2 = vt [tid][2];  // pred point
        float m1 = 3.4e38f, m2 = 3.4e38f;
#pragma unroll 4
        for (int k = 0; k < 200; k++) {
            float a0 = x0 - vt[k][0], a1 = x1 - vt[k][1], a2 = x2 - vt[k][2];
            m1 = fminf(m1, a0 * a0 + a1 * a1 + a2 * a2);
            float b0 = vtg[k][0] - y0, b1 = vtg[k][1] - y1, b2 = vtg[k][2] - y2;
            m2 = fminf(m2, b0 * b0 + b1 * b1 + b2 * b2);
        }
        cham = m1 + m2;
    }
    if (tid < 68) {
        const float* nm = normals + (size_t)n * (68 * 68) + tid;
        float s = 0.f;
#pragma unroll 4
        for (int i = 0; i < 68; i++) s += nm[i * 68];
        float d0 = vtg[tid][0] - vt[tid][0];
        float d1 = vtg[tid][1] - vt[tid][1];
        float d2 = vtg[tid][2] - vt[tid][2];
        nwl = s * (d0 * d0 + d1 * d1 + d2 * d2);
    }

    // ---- 6. combine + deterministic block reduce ----
    const float k_wpdc = 1.f / (128.f * 62.f);
    const float k_vdc  = 3.f * 0.001f / (128.f * 200.f);
    const float k_nwl  = 3.f * 0.001f / (128.f * 68.f * 3.f);
    float tot = wpdc * k_wpdc + cham * k_vdc + nwl * k_nwl;
    red[tid] = tot;
    __syncthreads();
#pragma unroll
    for (int o = NT / 2; o; o >>= 1) {
        if (tid < o) red[tid] += red[tid + o];
        __syncthreads();
    }

    // ---- 7. last block folds the 128 partials (fixed order -> deterministic) ----
    if (tid == 0) {
        g_partials[n] = red[0];
        __threadfence();
        unsigned int old = atomicAdd(&g_count, 1u);
        s_last = (old == BATCH - 1);
    }
    __syncthreads();
    if (s_last) {
        __threadfence();
        red[tid] = (tid < BATCH) ? g_partials[tid] : 0.f;
        __syncthreads();
#pragma unroll
        for (int o = 64; o; o >>= 1) {
            if (tid < o) red[tid] += red[tid + o];
            __syncthreads();
        }
        if (tid == 0) { out[0] = red[0]; g_count = 0; }
    }
}

extern "C" void kernel_launch(void* const* d_in, const int* in_sizes, int n_in,
                              void* d_out, int out_size)
{
    (void)in_sizes; (void)n_in; (void)out_size;
    loss_main<<<BATCH, NT>>>(
        (const float*)d_in[0],   // input
        (const float*)d_in[1],   // target
        (const float*)d_in[2],   // normals
        (const float*)d_in[3],   // param_mean
        (const float*)d_in[4],   // param_std
        (const float*)d_in[5],   // u
        (const float*)d_in[6],   // w_shp
        (const float*)d_in[7],   // w_exp
        (const int*)d_in[8],     // keyindex
        (const int*)d_in[9],     // resample_idx_w
        (const int*)d_in[10],    // resample_idx_v
        (float*)d_out);
}

// round 3
// speedup vs baseline: 1.1209x; 1.1209x over previous
#include <cuda_runtime.h>

#define BATCH 128
#define NT 256

__device__ float g_partials[BATCH];
__device__ float g_wcol[50];
__device__ unsigned int g_count = 0;
__device__ int g_wflag = 0;

__device__ __forceinline__ float warp_sum(float v) {
#pragma unroll
    for (int o = 16; o; o >>= 1) v += __shfl_down_sync(0xffffffffu, v, o);
    return v;
}

// grid = BATCH+1. Blocks 0..127: one batch element each. Block 128: column norms.
__global__ __launch_bounds__(NT, 1)
void loss_main(const float* __restrict__ input,
               const float* __restrict__ target,
               const float* __restrict__ normals,
               const float* __restrict__ param_mean,
               const float* __restrict__ param_std,
               const float* __restrict__ u,
               const float* __restrict__ w_shp,
               const float* __restrict__ w_exp,
               const int*   __restrict__ keyindex,
               const int*   __restrict__ ridx_w,
               const int*   __restrict__ ridx_v,
               float* __restrict__ out)
{
    const int tid  = threadIdx.x;
    const int lane = tid & 31;
    const int wid  = tid >> 5;

    // ================= dedicated block: batch-independent w_cat column norms =================
    if (blockIdx.x == BATCH) {
        __shared__ float cpart[8][50];
        float csq[50];
#pragma unroll
        for (int k = 0; k < 50; k++) csq[k] = 0.f;
        for (int l = tid; l < 600; l += NT) {
            int j = l / 3, c = l - 3 * j;
            int vid = (j < 68) ? keyindex[j] : ridx_w[j - 68];
            size_t r = 3 * (size_t)vid + c;
            const float4* w4 = (const float4*)(w_shp + r * 40);
#pragma unroll
            for (int q = 0; q < 10; q++) {
                float4 v = w4[q];
                csq[4*q+0] += v.x*v.x; csq[4*q+1] += v.y*v.y;
                csq[4*q+2] += v.z*v.z; csq[4*q+3] += v.w*v.w;
            }
            const float2* e2 = (const float2*)(w_exp + r * 10);
#pragma unroll
            for (int q = 0; q < 5; q++) {
                float2 v = e2[q];
                csq[40+2*q] += v.x*v.x; csq[41+2*q] += v.y*v.y;
            }
        }
#pragma unroll
        for (int k = 0; k < 50; k++) {
            float v = warp_sum(csq[k]);
            if (lane == 0) cpart[wid][k] = v;
        }
        __syncthreads();
        if (tid < 50) {
            float s = 0.f;
#pragma unroll
            for (int w = 0; w < 8; w++) s += cpart[w][tid];
            g_wcol[tid] = sqrtf(s);
        }
        __threadfence();
        __syncthreads();
        if (tid == 0) atomicExch(&g_wflag, 1);
        return;
    }

    // ================= per-batch block =================
    const int n = blockIdx.x;

    __shared__ float sp[62], spg[62];
    __shared__ float bv[600], bvg[600];
    __shared__ float tn_w[8][3];
    __shared__ float tnsq[3];
    __shared__ float4 vt4[200], vtg4[200];
    __shared__ float red[NT];
    __shared__ int   s_last;

    // ---- 0. denormalize params ----
    if (tid < 62) {
        float st = param_std[tid], mn = param_mean[tid];
        sp[tid]  = input [n * 62 + tid] * st + mn;
        spg[tid] = target[n * 62 + tid] * st + mn;
    }
    __syncthreads();

    // ---- 1. kmix_w pass: pred base verts -> tmpv sq-norms.
    //         Keypoint rows (l<204) also compute gt verts -> bv/bvg (shared with kmix_v).
    float tn0 = 0.f, tn1 = 0.f, tn2 = 0.f;
    for (int l = tid; l < 600; l += NT) {
        int j = l / 3, c = l - 3 * j;
        int vid = (j < 68) ? keyindex[j] : ridx_w[j - 68];
        size_t r = 3 * (size_t)vid + c;
        float uu = u[r];
        const float4* w4 = (const float4*)(w_shp + r * 40);
        const float2* e2 = (const float2*)(w_exp + r * 10);
        float s = uu, sg = uu;
#pragma unroll
        for (int q = 0; q < 10; q++) {
            float4 v = w4[q];
            s  += v.x * sp [12+4*q] + v.y * sp [13+4*q] + v.z * sp [14+4*q] + v.w * sp [15+4*q];
            sg += v.x * spg[12+4*q] + v.y * spg[13+4*q] + v.z * spg[14+4*q] + v.w * spg[15+4*q];
        }
#pragma unroll
        for (int q = 0; q < 5; q++) {
            float2 v = e2[q];
            s  += v.x * sp [52+2*q] + v.y * sp [53+2*q];
            sg += v.x * spg[52+2*q] + v.y * spg[53+2*q];
        }
        if (l < 204) { bv[l] = s; bvg[l] = sg; }
        float s2 = s * s;
        if (c == 0) tn0 += s2; else if (c == 1) tn1 += s2; else tn2 += s2;
    }
    tn0 = warp_sum(tn0); tn1 = warp_sum(tn1); tn2 = warp_sum(tn2);
    if (lane == 0) { tn_w[wid][0] = tn0; tn_w[wid][1] = tn1; tn_w[wid][2] = tn2; }

    // ---- 2. remaining kmix_v rows (ridx_v), pred + gt ----
    for (int l = 204 + tid; l < 600; l += NT) {
        int j = l / 3, c = l - 3 * j;
        int vid = ridx_v[j - 68];
        size_t r = 3 * (size_t)vid + c;
        float uu = u[r];
        const float4* w4 = (const float4*)(w_shp + r * 40);
        const float2* e2 = (const float2*)(w_exp + r * 10);
        float s = uu, sg = uu;
#pragma unroll
        for (int q = 0; q < 10; q++) {
            float4 v = w4[q];
            s  += v.x * sp [12+4*q] + v.y * sp [13+4*q] + v.z * sp [14+4*q] + v.w * sp [15+4*q];
            sg += v.x * spg[12+4*q] + v.y * spg[13+4*q] + v.z * spg[14+4*q] + v.w * spg[15+4*q];
        }
#pragma unroll
        for (int q = 0; q < 5; q++) {
            float2 v = e2[q];
            s  += v.x * sp [52+2*q] + v.y * sp [53+2*q];
            sg += v.x * spg[52+2*q] + v.y * spg[53+2*q];
        }
        bv[l] = s; bvg[l] = sg;
    }
    __syncthreads();
    if (tid < 3) {
        float s = 0.f;
#pragma unroll
        for (int w = 0; w < 8; w++) s += tn_w[w][tid];
        tnsq[tid] = s;
    }

    // ---- wait for column norms (usually already done) ----
    if (tid == 0) {
        while (atomicAdd(&g_wflag, 0) == 0) __nanosleep(64);
    }
    __syncthreads();
    __threadfence();  // acquire: g_wcol reads below see the producer's writes

    // ---- 3. weights + wpdc ----
    float wj = 0.f;
    if (tid < 62) {
        float pd = fabsf(sp[tid] - spg[tid]);
        if (tid < 11) {
            int cc = tid & 3;
            float sc = (cc < 3) ? sqrtf(tnsq[cc]) : 14.142135623730951f;  // sqrt(200)
            wj = pd * sc + 1e-6f;
        } else if (tid == 11) {
            wj = 1e-6f;
        } else {
            wj = 0.00057339936f * pd * g_wcol[tid - 12] + 1e-6f;
        }
    }
    red[tid] = wj;
    __syncthreads();
#pragma unroll
    for (int o = NT / 2; o; o >>= 1) {
        if (tid < o) red[tid] = fmaxf(red[tid], red[tid + o]);
        __syncthreads();
    }
    float wmax = red[0];
    __syncthreads();

    float wpdc = 0.f;
    if (tid < 62 && tid != 11) {
        float d = input[n * 62 + tid] - target[n * 62 + tid];
        wpdc = (wj / wmax) * d * d;
    }

    // ---- 4. rotate kmix_v verts (y-flip cancels in all downstream uses) ----
    if (tid < 200) {
        float b0 = bv [3*tid], b1 = bv [3*tid+1], b2 = bv [3*tid+2];
        float c0 = bvg[3*tid], c1 = bvg[3*tid+1], c2 = bvg[3*tid+2];
        float4 o1, o2;
        o1.x = sp [0]*b0 + sp [1]*b1 + sp [2]*b2 + sp [3];
        o1.y = sp [4]*b0 + sp [5]*b1 + sp [6]*b2 + sp [7];
        o1.z = sp [8]*b0 + sp [9]*b1 + sp[10]*b2 + sp[11];
        o1.w = 0.f;
        o2.x = spg[0]*c0 + spg[1]*c1 + spg[2]*c2 + spg[3];
        o2.y = spg[4]*c0 + spg[5]*c1 + spg[6]*c2 + spg[7];
        o2.z = spg[8]*c0 + spg[9]*c1 + spg[10]*c2 + spg[11];
        o2.w = 0.f;
        vt4[tid] = o1; vtg4[tid] = o2;
    }
    __syncthreads();

    // ---- 5. chamfer (200x200) + nwl ----
    float cham = 0.f, nwl = 0.f;
    if (tid < 200) {
        float4 X = vtg4[tid];  // gt point
        float4 Y = vt4 [tid];  // pred point
        float m1 = 3.4e38f, m2 = 3.4e38f;
#pragma unroll 5
        for (int k = 0; k < 200; k++) {
            float4 a = vt4[k];
            float d0 = X.x - a.x, d1 = X.y - a.y, d2 = X.z - a.z;
            m1 = fminf(m1, d0*d0 + d1*d1 + d2*d2);
            float4 b = vtg4[k];
            float e0 = b.x - Y.x, e1 = b.y - Y.y, e2 = b.z - Y.z;
            m2 = fminf(m2, e0*e0 + e1*e1 + e2*e2);
        }
        cham = m1 + m2;
    }
    if (tid < 68) {
        const float* nm = normals + (size_t)n * (68 * 68) + tid;
        float s = 0.f;
#pragma unroll 4
        for (int i = 0; i < 68; i++) s += nm[i * 68];
        float d0 = vtg4[tid].x - vt4[tid].x;
        float d1 = vtg4[tid].y - vt4[tid].y;
        float d2 = vtg4[tid].z - vt4[tid].z;
        nwl = s * (d0*d0 + d1*d1 + d2*d2);
    }

    // ---- 6. combine + deterministic block reduce ----
    const float k_wpdc = 1.f / (128.f * 62.f);
    const float k_vdc  = 3.f * 0.001f / (128.f * 200.f);
    const float k_nwl  = 3.f * 0.001f / (128.f * 68.f * 3.f);
    red[tid] = wpdc * k_wpdc + cham * k_vdc + nwl * k_nwl;
    __syncthreads();
#pragma unroll
    for (int o = NT / 2; o; o >>= 1) {
        if (tid < o) red[tid] += red[tid + o];
        __syncthreads();
    }

    // ---- 7. last batch block folds the 128 partials (fixed order) ----
    if (tid == 0) {
        g_partials[n] = red[0];
        __threadfence();
        unsigned int old = atomicAdd(&g_count, 1u);
        s_last = (old == BATCH - 1);
    }
    __syncthreads();
    if (s_last) {
        __threadfence();
        red[tid] = (tid < BATCH) ? g_partials[tid] : 0.f;
        __syncthreads();
#pragma unroll
        for (int o = 64; o; o >>= 1) {
            if (tid < o) red[tid] += red[tid + o];
            __syncthreads();
        }
        if (tid == 0) { out[0] = red[0]; g_count = 0; g_wflag = 0; }
    }
}

extern "C" void kernel_launch(void* const* d_in, const int* in_sizes, int n_in,
                              void* d_out, int out_size)
{
    (void)in_sizes; (void)n_in; (void)out_size;
    loss_main<<<BATCH + 1, NT>>>(
        (const float*)d_in[0],   // input
        (const float*)d_in[1],   // target
        (const float*)d_in[2],   // normals
        (const float*)d_in[3],   // param_mean
        (const float*)d_in[4],   // param_std
        (const float*)d_in[5],   // u
        (const float*)d_in[6],   // w_shp
        (const float*)d_in[7],   // w_exp
        (const int*)d_in[8],     // keyindex
        (const int*)d_in[9],     // resample_idx_w
        (const int*)d_in[10],    // resample_idx_v
        (float*)d_out);
}

// round 4
// speedup vs baseline: 1.1224x; 1.0013x over previous
#include <cuda_runtime.h>

#define BATCH 128
#define NT 512

__device__ float g_partials[BATCH];
__device__ float g_wcol[50];
__device__ unsigned int g_count = 0;
__device__ int g_wflag = 0;

__device__ __forceinline__ float warp_sum(float v) {
#pragma unroll
    for (int o = 16; o; o >>= 1) v += __shfl_down_sync(0xffffffffu, v, o);
    return v;
}

// grid = BATCH+1. Blocks 0..127: one batch element. Block 128: w_cat column norms.
__global__ __launch_bounds__(NT, 1)
void loss_main(const float* __restrict__ input,
               const float* __restrict__ target,
               const float* __restrict__ normals,
               const float* __restrict__ param_mean,
               const float* __restrict__ param_std,
               const float* __restrict__ u,
               const float* __restrict__ w_shp,
               const float* __restrict__ w_exp,
               const int*   __restrict__ keyindex,
               const int*   __restrict__ ridx_w,
               const int*   __restrict__ ridx_v,
               float* __restrict__ out)
{
    const int tid  = threadIdx.x;
    const int lane = tid & 31;
    const int wid  = tid >> 5;

    // ============ dedicated block: batch-independent w_cat column norms ============
    // Column-major: warp w owns columns c = w + 16k (k=0..3, c<50); lanes stride rows.
    if (blockIdx.x == BATCH) {
        __shared__ int srow[600];
        for (int l = tid; l < 600; l += NT) {
            int j = l / 3, c = l - 3 * j;
            int vid = (j < 68) ? keyindex[j] : ridx_w[j - 68];
            srow[l] = 3 * vid + c;
        }
        __syncthreads();
        float acc[4] = {0.f, 0.f, 0.f, 0.f};
#pragma unroll 1
        for (int rl = lane; rl < 600; rl += 32) {
            size_t r = (size_t)srow[rl];
            const float* ws = w_shp + r * 40;
            const float* we = w_exp + r * 10;
#pragma unroll
            for (int k = 0; k < 4; k++) {
                int c = wid + 16 * k;
                if (c < 50) {
                    float v = (c < 40) ? ws[c] : we[c - 40];
                    acc[k] += v * v;
                }
            }
        }
#pragma unroll
        for (int k = 0; k < 4; k++) {
            float v = warp_sum(acc[k]);
            int c = wid + 16 * k;
            if (lane == 0 && c < 50) g_wcol[c] = sqrtf(v);
        }
        __threadfence();
        __syncthreads();
        if (tid == 0) atomicExch(&g_wflag, 1);
        return;
    }

    // ============ per-batch block ============
    const int n = blockIdx.x;

    __shared__ float sp[62], spg[62];
    __shared__ float bv[600], bvg[600];
    __shared__ float tn_w[16][3];
    __shared__ float tnsq[3];
    __shared__ float4 vt4[200], vtg4[200];
    __shared__ float wred[64];
    __shared__ float wsum[16];
    __shared__ float s_wmax;
    __shared__ int   s_last;

    // ---- 0. denormalize params ----
    if (tid < 62) {
        float st = param_std[tid], mn = param_mean[tid];
        sp[tid]  = input [n * 62 + tid] * st + mn;
        spg[tid] = target[n * 62 + tid] * st + mn;
    }
    __syncthreads();

    // ---- 1. kmix_w pass: pred verts -> tmpv sq-norms; keypoint rows (l<204) also gt. ----
    float tn0 = 0.f, tn1 = 0.f, tn2 = 0.f;
    for (int l = tid; l < 600; l += NT) {
        int j = l / 3, c = l - 3 * j;
        int vid = (j < 68) ? keyindex[j] : ridx_w[j - 68];
        size_t r = 3 * (size_t)vid + c;
        const float4* w4 = (const float4*)(w_shp + r * 40);
        const float2* e2 = (const float2*)(w_exp + r * 10);
        float uu = u[r];
        float s;
        if (l < 204) {
            float sa = uu, sb = 0.f, ga = uu, gb = 0.f;
#pragma unroll
            for (int q = 0; q < 10; q += 2) {
                float4 v0 = w4[q], v1 = w4[q + 1];
                sa += v0.x*sp [12+4*q] + v0.y*sp [13+4*q] + v0.z*sp [14+4*q] + v0.w*sp [15+4*q];
                sb += v1.x*sp [16+4*q] + v1.y*sp [17+4*q] + v1.z*sp [18+4*q] + v1.w*sp [19+4*q];
                ga += v0.x*spg[12+4*q] + v0.y*spg[13+4*q] + v0.z*spg[14+4*q] + v0.w*spg[15+4*q];
                gb += v1.x*spg[16+4*q] + v1.y*spg[17+4*q] + v1.z*spg[18+4*q] + v1.w*spg[19+4*q];
            }
#pragma unroll
            for (int q = 0; q < 5; q++) {
                float2 v = e2[q];
                sa += v.x*sp [52+2*q] + v.y*sp [53+2*q];
                ga += v.x*spg[52+2*q] + v.y*spg[53+2*q];
            }
            s = sa + sb;
            bv[l] = s; bvg[l] = ga + gb;
        } else {
            float sa = uu, sb = 0.f;
#pragma unroll
            for (int q = 0; q < 10; q += 2) {
                float4 v0 = w4[q], v1 = w4[q + 1];
                sa += v0.x*sp[12+4*q] + v0.y*sp[13+4*q] + v0.z*sp[14+4*q] + v0.w*sp[15+4*q];
                sb += v1.x*sp[16+4*q] + v1.y*sp[17+4*q] + v1.z*sp[18+4*q] + v1.w*sp[19+4*q];
            }
#pragma unroll
            for (int q = 0; q < 5; q++) {
                float2 v = e2[q];
                sa += v.x*sp[52+2*q] + v.y*sp[53+2*q];
            }
            s = sa + sb;
        }
        float s2 = s * s;
        if (c == 0) tn0 += s2; else if (c == 1) tn1 += s2; else tn2 += s2;
    }
    tn0 = warp_sum(tn0); tn1 = warp_sum(tn1); tn2 = warp_sum(tn2);
    if (lane == 0) { tn_w[wid][0] = tn0; tn_w[wid][1] = tn1; tn_w[wid][2] = tn2; }

    // ---- 2. remaining kmix_v rows (ridx_v), pred + gt ----
    if (tid < 396) {
        int l = 204 + tid;
        int j = l / 3, c = l - 3 * j;
        int vid = ridx_v[j - 68];
        size_t r = 3 * (size_t)vid + c;
        const float4* w4 = (const float4*)(w_shp + r * 40);
        const float2* e2 = (const float2*)(w_exp + r * 10);
        float uu = u[r];
        float sa = uu, sb = 0.f, ga = uu, gb = 0.f;
#pragma unroll
        for (int q = 0; q < 10; q += 2) {
            float4 v0 = w4[q], v1 = w4[q + 1];
            sa += v0.x*sp [12+4*q] + v0.y*sp [13+4*q] + v0.z*sp [14+4*q] + v0.w*sp [15+4*q];
            sb += v1.x*sp [16+4*q] + v1.y*sp [17+4*q] + v1.z*sp [18+4*q] + v1.w*sp [19+4*q];
            ga += v0.x*spg[12+4*q] + v0.y*spg[13+4*q] + v0.z*spg[14+4*q] + v0.w*spg[15+4*q];
            gb += v1.x*spg[16+4*q] + v1.y*spg[17+4*q] + v1.z*spg[18+4*q] + v1.w*spg[19+4*q];
        }
#pragma unroll
        for (int q = 0; q < 5; q++) {
            float2 v = e2[q];
            sa += v.x*sp [52+2*q] + v.y*sp [53+2*q];
            ga += v.x*spg[52+2*q] + v.y*spg[53+2*q];
        }
        bv[l] = sa + sb; bvg[l] = ga + gb;
    }
    __syncthreads();
    if (tid < 3) {
        float s = 0.f;
#pragma unroll
        for (int w = 0; w < 16; w++) s += tn_w[w][tid];
        tnsq[tid] = s;
    }

    // ---- wait for column norms (usually already done) ----
    if (tid == 0) {
        while (atomicAdd(&g_wflag, 0) == 0) __nanosleep(64);
    }
    __syncthreads();
    __threadfence();  // acquire for g_wcol

    // ---- 3. weights + wpdc ----
    float wj = 0.f;
    if (tid < 62) {
        float pd = fabsf(sp[tid] - spg[tid]);
        if (tid < 11) {
            int cc = tid & 3;
            float sc = (cc < 3) ? sqrtf(tnsq[cc]) : 14.142135623730951f;  // sqrt(200)
            wj = pd * sc + 1e-6f;
        } else if (tid == 11) {
            wj = 1e-6f;
        } else {
            wj = 0.00057339936f * pd * g_wcol[tid - 12] + 1e-6f;
        }
    }
    if (tid < 64) wred[tid] = wj;  // tid 62,63 write 0
    __syncthreads();
    if (wid == 0) {
        float v = fmaxf(wred[lane], wred[lane + 32]);
#pragma unroll
        for (int o = 16; o; o >>= 1) v = fmaxf(v, __shfl_down_sync(0xffffffffu, v, o));
        if (lane == 0) s_wmax = v;
    }
    __syncthreads();
    float wmax = s_wmax;

    float wpdc = 0.f;
    if (tid < 62 && tid != 11) {
        float d = input[n * 62 + tid] - target[n * 62 + tid];
        wpdc = (wj / wmax) * d * d;
    }

    // ---- 4. rotate kmix_v verts (y-flip cancels in all downstream uses) ----
    if (tid < 200) {
        float b0 = bv [3*tid], b1 = bv [3*tid+1], b2 = bv [3*tid+2];
        float c0 = bvg[3*tid], c1 = bvg[3*tid+1], c2 = bvg[3*tid+2];
        float4 o1, o2;
        o1.x = sp [0]*b0 + sp [1]*b1 + sp [2]*b2 + sp [3];
        o1.y = sp [4]*b0 + sp [5]*b1 + sp [6]*b2 + sp [7];
        o1.z = sp [8]*b0 + sp [9]*b1 + sp[10]*b2 + sp[11];
        o1.w = 0.f;
        o2.x = spg[0]*c0 + spg[1]*c1 + spg[2]*c2 + spg[3];
        o2.y = spg[4]*c0 + spg[5]*c1 + spg[6]*c2 + spg[7];
        o2.z = spg[8]*c0 + spg[9]*c1 + spg[10]*c2 + spg[11];
        o2.w = 0.f;
        vt4[tid] = o1; vtg4[tid] = o2;
    }
    __syncthreads();

    // ---- 5. chamfer on warps 0-6 (tid<200); nwl on warps 13-15 (tid 440-507) -- concurrent ----
    float cham = 0.f, nwl = 0.f;
    if (tid < 200) {
        float4 X = vtg4[tid];  // gt point
        float4 Y = vt4 [tid];  // pred point
        float m1 = 3.4e38f, m2 = 3.4e38f;
#pragma unroll 5
        for (int k = 0; k < 200; k++) {
            float4 a = vt4[k];
            float d0 = X.x - a.x, d1 = X.y - a.y, d2 = X.z - a.z;
            m1 = fminf(m1, d0*d0 + d1*d1 + d2*d2);
            float4 b = vtg4[k];
            float e0 = b.x - Y.x, e1 = b.y - Y.y, e2 = b.z - Y.z;
            m2 = fminf(m2, e0*e0 + e1*e1 + e2*e2);
        }
        cham = m1 + m2;
    } else if (tid >= 440 && tid < 508) {
        int t = tid - 440;
        const float* nm = normals + (size_t)n * (68 * 68) + t;
        float s = 0.f;
#pragma unroll 4
        for (int i = 0; i < 68; i++) s += nm[i * 68];
        float d0 = vtg4[t].x - vt4[t].x;
        float d1 = vtg4[t].y - vt4[t].y;
        float d2 = vtg4[t].z - vt4[t].z;
        nwl = s * (d0*d0 + d1*d1 + d2*d2);
    }

    // ---- 6. combine + warp-shuffle block reduce ----
    const float k_wpdc = 1.f / (128.f * 62.f);
    const float k_vdc  = 3.f * 0.001f / (128.f * 200.f);
    const float k_nwl  = 3.f * 0.001f / (128.f * 68.f * 3.f);
    float tot = wpdc * k_wpdc + cham * k_vdc + nwl * k_nwl;
    tot = warp_sum(tot);
    if (lane == 0) wsum[wid] = tot;
    __syncthreads();

    // ---- 7. finalize: partial out, last block folds 128 partials (fixed order) ----
    if (tid == 0) {
        float b = 0.f;
#pragma unroll
        for (int w = 0; w < 16; w++) b += wsum[w];
        g_partials[n] = b;
        __threadfence();
        unsigned int old = atomicAdd(&g_count, 1u);
        s_last = (old == BATCH - 1);
    }
    __syncthreads();
    if (s_last) {
        __threadfence();
        if (wid == 0) {
            float v = g_partials[lane] + g_partials[lane + 32]
                    + g_partials[lane + 64] + g_partials[lane + 96];
#pragma unroll
            for (int o = 16; o; o >>= 1) v += __shfl_down_sync(0xffffffffu, v, o);
            if (lane == 0) { out[0] = v; g_count = 0; g_wflag = 0; }
        }
    }
}

extern "C" void kernel_launch(void* const* d_in, const int* in_sizes, int n_in,
                              void* d_out, int out_size)
{
    (void)in_sizes; (void)n_in; (void)out_size;
    loss_main<<<BATCH + 1, NT>>>(
        (const float*)d_in[0],   // input
        (const float*)d_in[1],   // target
        (const float*)d_in[2],   // normals
        (const float*)d_in[3],   // param_mean
        (const float*)d_in[4],   // param_std
        (const float*)d_in[5],   // u
        (const float*)d_in[6],   // w_shp
        (const float*)d_in[7],   // w_exp
        (const int*)d_in[8],     // keyindex
        (const int*)d_in[9],     // resample_idx_w
        (const int*)d_in[10],    // resample_idx_v
        (float*)d_out);
}